// round 2
// baseline (speedup 1.0000x reference)
#include <cuda_runtime.h>
#include <math.h>
#include <stdint.h>

// ---------------------------------------------------------------------------
// NormalVariationBoundaryLoss
//   loss = sum_p( ce_p * w_p * vm_p ) / max(sum_p vm_p, 1)
//   w_p  = 1 + 3 * clip((diff_p - dmin)/(dmax - dmin + 1e-6), 0, 1)
//   diff = 1 - clip(cos(normalize(n_p), normalize(voxel_sum_n)), -1, 1)
//   voxel grouping == group by (x,y,z,batch): the reference int64 hash is
//   injective over x,y,z in [0,128), batch in [0,8), so a 30-bit packed key
//   + open-addressing hash table reproduces unique+inverse exactly.
//   Integer inputs may arrive as int32 or int64 -> runtime dtype detection.
// ---------------------------------------------------------------------------

#define TABLE_BITS 22
#define TSIZE (1u << TABLE_BITS)
#define NMAX 2097152

// zero-initialized device scratch (allocation-free per harness rules)
__device__ unsigned int g_keys[TSIZE];       // 0 = empty, else packed_key+1
__device__ float        g_sums[3u * TSIZE];  // per-slot sum of normals
__device__ int          g_slot[NMAX];
__device__ float        g_diff[NMAX];
__device__ unsigned int g_dmin_bits;
__device__ unsigned int g_dmax_bits;
__device__ double       g_loss;
__device__ double       g_vm;
__device__ unsigned int g_odd_or;            // 0 => int inputs are int64

// ---------------------------------------------------------------------------
__global__ void init_kernel() {
    g_dmin_bits = 0x7f800000u;  // +inf
    g_dmax_bits = 0u;           // 0.0f (diff >= 0 for valid points)
    g_loss = 0.0;
    g_vm   = 0.0;
    g_odd_or = 0u;
}

// ---------------------------------------------------------------------------
// Detect int32 vs int64: OR all odd 32-bit words of the first n32 words of
// grid_coord. int64 buffer (values < 2^31) => all odd words are zero.
// Reads only n32 words, which is in-bounds for BOTH dtypes.
__global__ void detect_kernel(const unsigned int* __restrict__ w, int n32) {
    unsigned int acc = 0u;
    int stride = gridDim.x * blockDim.x;
    for (int i = blockIdx.x * blockDim.x + threadIdx.x; 2 * i + 1 < n32; i += stride)
        acc |= w[2 * i + 1];
#pragma unroll
    for (int o = 16; o; o >>= 1) acc |= __shfl_xor_sync(0xffffffffu, acc, o);
    if ((threadIdx.x & 31) == 0 && acc) atomicOr(&g_odd_or, acc);
}

__device__ __forceinline__ long long ld_idx(const void* p, long long i, bool is64) {
    return is64 ? ((const long long*)p)[i] : (long long)((const int*)p)[i];
}

// ---------------------------------------------------------------------------
// Per-point: insert voxel key into hash table, accumulate normal sums.
__global__ void hash_kernel(const void* __restrict__ gc,
                            const void* __restrict__ batch,
                            const void* __restrict__ target,
                            const float* __restrict__ normal,
                            int n) {
    const bool is64 = (g_odd_or == 0u);
    int p = blockIdx.x * blockDim.x + threadIdx.x;
    if (p >= n) return;

    long long t = ld_idx(target, p, is64);
    if (t == -1LL) { g_slot[p] = -1; return; }

    unsigned int x = (unsigned int)ld_idx(gc, 3LL * p + 0, is64);
    unsigned int y = (unsigned int)ld_idx(gc, 3LL * p + 1, is64);
    unsigned int z = (unsigned int)ld_idx(gc, 3LL * p + 2, is64);
    unsigned int b = (unsigned int)ld_idx(batch, p, is64);
    // 9 bits per coord, 3 bits batch -> injective for x,y,z<512, b<8
    unsigned int key = ((b << 27) | (x << 18) | (y << 9) | z) + 1u;

    unsigned int h = (key * 2654435761u) >> (32 - TABLE_BITS);
    while (true) {
        unsigned int prev = atomicCAS(&g_keys[h], 0u, key);
        if (prev == 0u || prev == key) break;
        h = (h + 1u) & (TSIZE - 1u);
    }
    g_slot[p] = (int)h;

    float nx = normal[3 * p + 0];
    float ny = normal[3 * p + 1];
    float nz = normal[3 * p + 2];
    atomicAdd(&g_sums[3u * h + 0u], nx);
    atomicAdd(&g_sums[3u * h + 1u], ny);
    atomicAdd(&g_sums[3u * h + 2u], nz);
}

// ---------------------------------------------------------------------------
// Per-point: diff = 1 - cos(normal, voxel_mean_normal); global min/max reduce.
// Note l2_normalize(sum/cnt) == l2_normalize(sum), so counts are not needed.
__global__ void diff_kernel(const float* __restrict__ normal, int n) {
    __shared__ float sh_min[8];
    __shared__ float sh_max[8];

    float lmin = INFINITY;
    float lmax = -INFINITY;

    int stride = gridDim.x * blockDim.x;
    for (int p = blockIdx.x * blockDim.x + threadIdx.x; p < n; p += stride) {
        int s = g_slot[p];
        float d;
        if (s < 0) {
            d = -1.f;  // invalid marker
        } else {
            float sx = g_sums[3 * s + 0];
            float sy = g_sums[3 * s + 1];
            float sz = g_sums[3 * s + 2];
            float nx = normal[3 * p + 0];
            float ny = normal[3 * p + 1];
            float nz = normal[3 * p + 2];
            float sn = sqrtf(sx * sx + sy * sy + sz * sz);
            float nn = sqrtf(nx * nx + ny * ny + nz * nz);
            float inv = 1.f / (fmaxf(sn, 1e-6f) * fmaxf(nn, 1e-6f));
            float c = (sx * nx + sy * ny + sz * nz) * inv;
            c = fminf(fmaxf(c, -1.f), 1.f);
            d = 1.f - c;
            lmin = fminf(lmin, d);
            lmax = fmaxf(lmax, d);
        }
        g_diff[p] = d;
    }

#pragma unroll
    for (int o = 16; o; o >>= 1) {
        lmin = fminf(lmin, __shfl_xor_sync(0xffffffffu, lmin, o));
        lmax = fmaxf(lmax, __shfl_xor_sync(0xffffffffu, lmax, o));
    }
    int wid = threadIdx.x >> 5, lane = threadIdx.x & 31;
    if (lane == 0) { sh_min[wid] = lmin; sh_max[wid] = lmax; }
    __syncthreads();
    if (wid == 0) {
        int nw = blockDim.x >> 5;
        lmin = (lane < nw) ? sh_min[lane] : INFINITY;
        lmax = (lane < nw) ? sh_max[lane] : -INFINITY;
#pragma unroll
        for (int o = 16; o; o >>= 1) {
            lmin = fminf(lmin, __shfl_xor_sync(0xffffffffu, lmin, o));
            lmax = fmaxf(lmax, __shfl_xor_sync(0xffffffffu, lmax, o));
        }
        if (lane == 0) {
            if (lmin <= 2.f) atomicMin(&g_dmin_bits, __float_as_uint(lmin));
            if (lmax >= 0.f) atomicMax(&g_dmax_bits, __float_as_uint(lmax));
        }
    }
}

// ---------------------------------------------------------------------------
// Warp per point: cross entropy (coalesced 128B row load), weight, loss sum.
// Also cleans the hash slots used this launch (table back to zero state).
__global__ void finalize_kernel(const float* __restrict__ pred,
                                const void* __restrict__ target,
                                int n, int C) {
    __shared__ double sh_loss[8];
    __shared__ double sh_cnt[8];

    const bool is64 = (g_odd_or == 0u);
    float dmin = __uint_as_float(g_dmin_bits);
    float dmax = __uint_as_float(g_dmax_bits);
    float invr = 1.f / (dmax - dmin + 1e-6f);

    int lane = threadIdx.x & 31;
    int gw   = (blockIdx.x * blockDim.x + threadIdx.x) >> 5;
    int nwrp = (gridDim.x * blockDim.x) >> 5;

    double lsum = 0.0;
    double lcnt = 0.0;

    for (int p = gw; p < n; p += nwrp) {
        float d = g_diff[p];
        int   s = g_slot[p];
        if (d >= 0.f) {
            const float* row = pred + (size_t)p * (size_t)C;
            long long t = ld_idx(target, p, is64);

            int iters = (C + 31) >> 5;
            if (iters > 8) iters = 8;  // C <= 256
            float xs[8];
            float m  = -INFINITY;
            float xt = 0.f;
#pragma unroll
            for (int i = 0; i < 8; i++) {
                if (i >= iters) break;
                int c = i * 32 + lane;
                float x = (c < C) ? row[c] : -INFINITY;
                xs[i] = x;
                m = fmaxf(m, x);
                if ((long long)c == t) xt = x;
            }
#pragma unroll
            for (int o = 16; o; o >>= 1) m = fmaxf(m, __shfl_xor_sync(0xffffffffu, m, o));
            float sum = 0.f;
#pragma unroll
            for (int i = 0; i < 8; i++) {
                if (i >= iters) break;
                sum += __expf(xs[i] - m);
            }
#pragma unroll
            for (int o = 16; o; o >>= 1) sum += __shfl_xor_sync(0xffffffffu, sum, o);
#pragma unroll
            for (int o = 16; o; o >>= 1) xt  += __shfl_xor_sync(0xffffffffu, xt, o);

            if (lane == 0) {
                float ce = m + __logf(sum) - xt;
                float dn = (d - dmin) * invr;
                dn = fminf(fmaxf(dn, 0.f), 1.f);
                float w = 1.f + 3.f * dn;
                lsum += (double)(ce * w);
                lcnt += 1.0;
            }
        }
        if (s >= 0 && lane == 0) {  // cleanup (same-value races are benign)
            g_keys[s] = 0u;
            g_sums[3 * s + 0] = 0.f;
            g_sums[3 * s + 1] = 0.f;
            g_sums[3 * s + 2] = 0.f;
        }
    }

    int wid = threadIdx.x >> 5;
    if (lane == 0) { sh_loss[wid] = lsum; sh_cnt[wid] = lcnt; }
    __syncthreads();
    if (wid == 0) {
        int nw = blockDim.x >> 5;
        lsum = (lane < nw) ? sh_loss[lane] : 0.0;
        lcnt = (lane < nw) ? sh_cnt[lane] : 0.0;
#pragma unroll
        for (int o = 16; o; o >>= 1) {
            lsum += __shfl_xor_sync(0xffffffffu, lsum, o);
            lcnt += __shfl_xor_sync(0xffffffffu, lcnt, o);
        }
        if (lane == 0) {
            atomicAdd(&g_loss, lsum);
            atomicAdd(&g_vm, lcnt);
        }
    }
}

// ---------------------------------------------------------------------------
__global__ void writeout_kernel(float* __restrict__ out) {
    double denom = g_vm > 1.0 ? g_vm : 1.0;
    out[0] = (float)(g_loss / denom);  // LOSS_WEIGHT = 1
}

// ---------------------------------------------------------------------------
extern "C" void kernel_launch(void* const* d_in, const int* in_sizes, int n_in,
                              void* d_out, int out_size) {
    const float* pred   = (const float*)d_in[0];
    const void*  target = d_in[1];
    const void*  gcoord = d_in[2];
    const float* normal = (const float*)d_in[3];
    const void*  batch  = d_in[4];
    float* out = (float*)d_out;

    int n = in_sizes[1];              // number of points
    int C = in_sizes[0] / n;          // number of classes (32)

    init_kernel<<<1, 1>>>();

    // dtype detection on grid_coord (n*3 32-bit words is in-bounds for both)
    detect_kernel<<<256, 256>>>((const unsigned int*)gcoord, n * 3);

    // Hash insert + normal accumulation: thread per point
    {
        int threads = 256;
        int blocks = (n + threads - 1) / threads;
        hash_kernel<<<blocks, threads>>>(gcoord, batch, target, normal, n);
    }

    // diff + min/max reduce (grid-stride, bounded atomics)
    {
        int threads = 256;
        int blocks = 1480;
        int need = (n + threads - 1) / threads;
        if (blocks > need) blocks = need;
        diff_kernel<<<blocks, threads>>>(normal, n);
    }

    // CE + weighted loss sum + hash cleanup (warp per point, grid-stride)
    {
        int threads = 256;
        int blocks = 2960;
        finalize_kernel<<<blocks, threads>>>(pred, target, n, C);
    }

    writeout_kernel<<<1, 1>>>(out);
}

// round 3
// speedup vs baseline: 1.0650x; 1.0650x over previous
#include <cuda_runtime.h>
#include <math.h>
#include <stdint.h>

// ---------------------------------------------------------------------------
// NormalVariationBoundaryLoss
//   loss = sum_p( ce_p * w_p * vm_p ) / max(sum_p vm_p, 1)
//   w_p  = 1 + 3 * clip((diff_p - dmin)/(dmax - dmin + 1e-6), 0, 1)
//   diff = 1 - clip(cos(normalize(n_p), normalize(voxel_sum_n)), -1, 1)
//   Voxel grouping == group by (x,y,z,batch); reference int64 hash is
//   injective over these ranges, so a 30-bit packed key + open-addressing
//   hash table reproduces unique+inverse exactly.
//   Interleaved 16B slots {key, sx, sy, sz}: one sector per point for
//   CAS + adds + gather. Cleanup = streaming clear (not scattered stores).
// ---------------------------------------------------------------------------

#define TABLE_BITS 22
#define TSIZE (1u << TABLE_BITS)
#define NMAX 2097152

// zero-initialized device scratch (allocation-free per harness rules)
__device__ uint4        g_table[TSIZE];   // {key(0=empty,else key+1), sx, sy, sz}
__device__ int          g_slot[NMAX];
__device__ float        g_diff[NMAX];
__device__ unsigned int g_dmin_bits;
__device__ unsigned int g_dmax_bits;
__device__ double       g_loss;
__device__ double       g_vm;
__device__ unsigned int g_odd_or;         // 0 => int inputs are int64

// ---------------------------------------------------------------------------
__global__ void init_kernel() {
    g_dmin_bits = 0x7f800000u;  // +inf
    g_dmax_bits = 0u;           // 0.0f (diff >= 0 for valid points)
    g_loss = 0.0;
    g_vm   = 0.0;
    g_odd_or = 0u;
}

// ---------------------------------------------------------------------------
// Detect int32 vs int64: OR all odd 32-bit words of the first n32 words of
// grid_coord. int64 little-endian (values < 2^31) => all odd words are zero.
// Reads only n32 words, in-bounds for BOTH dtypes.
__global__ void detect_kernel(const unsigned int* __restrict__ w, int n32) {
    unsigned int acc = 0u;
    int stride = gridDim.x * blockDim.x;
    for (int i = blockIdx.x * blockDim.x + threadIdx.x; 2 * i + 1 < n32; i += stride)
        acc |= w[2 * i + 1];
#pragma unroll
    for (int o = 16; o; o >>= 1) acc |= __shfl_xor_sync(0xffffffffu, acc, o);
    if ((threadIdx.x & 31) == 0 && acc) atomicOr(&g_odd_or, acc);
}

__device__ __forceinline__ long long ld_idx(const void* p, long long i, bool is64) {
    return is64 ? ((const long long*)p)[i] : (long long)((const int*)p)[i];
}

// ---------------------------------------------------------------------------
// Per-point: insert voxel key into hash table, accumulate normal sums.
// Slot layout: word0 = key+1 (0 empty), words1..3 = float sums.
__global__ void hash_kernel(const void* __restrict__ gc,
                            const void* __restrict__ batch,
                            const void* __restrict__ target,
                            const float* __restrict__ normal,
                            int n) {
    const bool is64 = (g_odd_or == 0u);
    int p = blockIdx.x * blockDim.x + threadIdx.x;
    if (p >= n) return;

    long long t = ld_idx(target, p, is64);
    if (t == -1LL) { g_slot[p] = -1; return; }

    unsigned int x = (unsigned int)ld_idx(gc, 3LL * p + 0, is64);
    unsigned int y = (unsigned int)ld_idx(gc, 3LL * p + 1, is64);
    unsigned int z = (unsigned int)ld_idx(gc, 3LL * p + 2, is64);
    unsigned int b = (unsigned int)ld_idx(batch, p, is64);
    // 9 bits per coord, 3 bits batch -> injective for x,y,z<512, b<8
    unsigned int key = ((b << 27) | (x << 18) | (y << 9) | z) + 1u;

    unsigned int* tbl = (unsigned int*)g_table;
    unsigned int h = (key * 2654435761u) >> (32 - TABLE_BITS);
    while (true) {
        unsigned int prev = atomicCAS(&tbl[4u * h], 0u, key);
        if (prev == 0u || prev == key) break;
        h = (h + 1u) & (TSIZE - 1u);
    }
    g_slot[p] = (int)h;

    float* fs = (float*)g_table + 4u * h;
    atomicAdd(fs + 1, normal[3 * p + 0]);
    atomicAdd(fs + 2, normal[3 * p + 1]);
    atomicAdd(fs + 3, normal[3 * p + 2]);
}

// ---------------------------------------------------------------------------
// Per-point: diff = 1 - cos(normal, voxel_mean_normal); global min/max reduce.
// l2_normalize(sum/cnt) == l2_normalize(sum), so counts are not needed.
__global__ void diff_kernel(const float* __restrict__ normal, int n) {
    __shared__ float sh_min[8];
    __shared__ float sh_max[8];

    float lmin = INFINITY;
    float lmax = -INFINITY;

    int stride = gridDim.x * blockDim.x;
    for (int p = blockIdx.x * blockDim.x + threadIdx.x; p < n; p += stride) {
        int s = g_slot[p];
        float d;
        if (s < 0) {
            d = -1.f;  // invalid marker
        } else {
            float4 f = ((const float4*)g_table)[s];  // one 16B gather
            float sx = f.y, sy = f.z, sz = f.w;
            float nx = normal[3 * p + 0];
            float ny = normal[3 * p + 1];
            float nz = normal[3 * p + 2];
            float sn = sqrtf(sx * sx + sy * sy + sz * sz);
            float nn = sqrtf(nx * nx + ny * ny + nz * nz);
            float inv = 1.f / (fmaxf(sn, 1e-6f) * fmaxf(nn, 1e-6f));
            float c = (sx * nx + sy * ny + sz * nz) * inv;
            c = fminf(fmaxf(c, -1.f), 1.f);
            d = 1.f - c;
            lmin = fminf(lmin, d);
            lmax = fmaxf(lmax, d);
        }
        g_diff[p] = d;
    }

#pragma unroll
    for (int o = 16; o; o >>= 1) {
        lmin = fminf(lmin, __shfl_xor_sync(0xffffffffu, lmin, o));
        lmax = fmaxf(lmax, __shfl_xor_sync(0xffffffffu, lmax, o));
    }
    int wid = threadIdx.x >> 5, lane = threadIdx.x & 31;
    if (lane == 0) { sh_min[wid] = lmin; sh_max[wid] = lmax; }
    __syncthreads();
    if (wid == 0) {
        int nw = blockDim.x >> 5;
        lmin = (lane < nw) ? sh_min[lane] : INFINITY;
        lmax = (lane < nw) ? sh_max[lane] : -INFINITY;
#pragma unroll
        for (int o = 16; o; o >>= 1) {
            lmin = fminf(lmin, __shfl_xor_sync(0xffffffffu, lmin, o));
            lmax = fmaxf(lmax, __shfl_xor_sync(0xffffffffu, lmax, o));
        }
        if (lane == 0) {
            if (lmin <= 2.f) atomicMin(&g_dmin_bits, __float_as_uint(lmin));
            if (lmax >= 0.f) atomicMax(&g_dmax_bits, __float_as_uint(lmax));
        }
    }
}

// ---------------------------------------------------------------------------
// Warp per point: cross entropy (coalesced 128B row load), weight, loss sum.
__global__ void finalize_kernel(const float* __restrict__ pred,
                                const void* __restrict__ target,
                                int n, int C) {
    __shared__ double sh_loss[8];
    __shared__ double sh_cnt[8];

    const bool is64 = (g_odd_or == 0u);
    float dmin = __uint_as_float(g_dmin_bits);
    float dmax = __uint_as_float(g_dmax_bits);
    float invr = 1.f / (dmax - dmin + 1e-6f);

    int lane = threadIdx.x & 31;
    int gw   = (blockIdx.x * blockDim.x + threadIdx.x) >> 5;
    int nwrp = (gridDim.x * blockDim.x) >> 5;

    double lsum = 0.0;
    double lcnt = 0.0;

    if (C == 32) {
        for (int p = gw; p < n; p += nwrp) {
            float d = g_diff[p];
            if (d < 0.f) continue;
            const float* row = pred + (size_t)p * 32u;
            long long t = ld_idx(target, p, is64);

            float x = row[lane];
            float m = x;
#pragma unroll
            for (int o = 16; o; o >>= 1) m = fmaxf(m, __shfl_xor_sync(0xffffffffu, m, o));
            float e = __expf(x - m);
#pragma unroll
            for (int o = 16; o; o >>= 1) e += __shfl_xor_sync(0xffffffffu, e, o);
            float xt = __shfl_sync(0xffffffffu, x, (int)t);

            if (lane == 0) {
                float ce = m + __logf(e) - xt;
                float dn = (d - dmin) * invr;
                dn = fminf(fmaxf(dn, 0.f), 1.f);
                lsum += (double)(ce * (1.f + 3.f * dn));
                lcnt += 1.0;
            }
        }
    } else {
        for (int p = gw; p < n; p += nwrp) {
            float d = g_diff[p];
            if (d < 0.f) continue;
            const float* row = pred + (size_t)p * (size_t)C;
            long long t = ld_idx(target, p, is64);

            int iters = (C + 31) >> 5;
            if (iters > 8) iters = 8;  // C <= 256
            float xs[8];
            float m  = -INFINITY;
            float xt = 0.f;
#pragma unroll
            for (int i = 0; i < 8; i++) {
                if (i >= iters) break;
                int c = i * 32 + lane;
                float x = (c < C) ? row[c] : -INFINITY;
                xs[i] = x;
                m = fmaxf(m, x);
                if ((long long)c == t) xt = x;
            }
#pragma unroll
            for (int o = 16; o; o >>= 1) m = fmaxf(m, __shfl_xor_sync(0xffffffffu, m, o));
            float sum = 0.f;
#pragma unroll
            for (int i = 0; i < 8; i++) {
                if (i >= iters) break;
                sum += __expf(xs[i] - m);
            }
#pragma unroll
            for (int o = 16; o; o >>= 1) sum += __shfl_xor_sync(0xffffffffu, sum, o);
#pragma unroll
            for (int o = 16; o; o >>= 1) xt  += __shfl_xor_sync(0xffffffffu, xt, o);

            if (lane == 0) {
                float ce = m + __logf(sum) - xt;
                float dn = (d - dmin) * invr;
                dn = fminf(fmaxf(dn, 0.f), 1.f);
                lsum += (double)(ce * (1.f + 3.f * dn));
                lcnt += 1.0;
            }
        }
    }

    int wid = threadIdx.x >> 5;
    if (lane == 0) { sh_loss[wid] = lsum; sh_cnt[wid] = lcnt; }
    __syncthreads();
    if (wid == 0) {
        int nw = blockDim.x >> 5;
        lsum = (lane < nw) ? sh_loss[lane] : 0.0;
        lcnt = (lane < nw) ? sh_cnt[lane] : 0.0;
#pragma unroll
        for (int o = 16; o; o >>= 1) {
            lsum += __shfl_xor_sync(0xffffffffu, lsum, o);
            lcnt += __shfl_xor_sync(0xffffffffu, lcnt, o);
        }
        if (lane == 0) {
            atomicAdd(&g_loss, lsum);
            atomicAdd(&g_vm, lcnt);
        }
    }
}

// ---------------------------------------------------------------------------
// Streaming clear of the hash table (returns scratch to zero state for the
// next graph replay). Pure coalesced 16B stores: ~67MB.
__global__ void clear_kernel() {
    uint4 z = make_uint4(0u, 0u, 0u, 0u);
    unsigned int stride = gridDim.x * blockDim.x;
    for (unsigned int i = blockIdx.x * blockDim.x + threadIdx.x; i < TSIZE; i += stride)
        g_table[i] = z;
}

// ---------------------------------------------------------------------------
__global__ void writeout_kernel(float* __restrict__ out) {
    double denom = g_vm > 1.0 ? g_vm : 1.0;
    out[0] = (float)(g_loss / denom);  // LOSS_WEIGHT = 1
}

// ---------------------------------------------------------------------------
extern "C" void kernel_launch(void* const* d_in, const int* in_sizes, int n_in,
                              void* d_out, int out_size) {
    const float* pred   = (const float*)d_in[0];
    const void*  target = d_in[1];
    const void*  gcoord = d_in[2];
    const float* normal = (const float*)d_in[3];
    const void*  batch  = d_in[4];
    float* out = (float*)d_out;

    int n = in_sizes[1];              // number of points
    int C = in_sizes[0] / n;          // number of classes (32)

    init_kernel<<<1, 1>>>();

    // dtype detection on grid_coord (n*3 32-bit words is in-bounds for both)
    detect_kernel<<<256, 256>>>((const unsigned int*)gcoord, n * 3);

    // Hash insert + normal accumulation: thread per point
    {
        int threads = 256;
        int blocks = (n + threads - 1) / threads;
        hash_kernel<<<blocks, threads>>>(gcoord, batch, target, normal, n);
    }

    // diff + min/max reduce (grid-stride, bounded atomics)
    {
        int threads = 256;
        int blocks = 1480;
        int need = (n + threads - 1) / threads;
        if (blocks > need) blocks = need;
        diff_kernel<<<blocks, threads>>>(normal, n);
    }

    // CE + weighted loss sum (warp per point, grid-stride)
    finalize_kernel<<<2960, 256>>>(pred, target, n, C);

    // streaming table clear (restores zero state for next replay)
    clear_kernel<<<1480, 256>>>();

    writeout_kernel<<<1, 1>>>(out);
}